// round 12
// baseline (speedup 1.0000x reference)
#include <cuda_runtime.h>

#define GEPS    1e-7f
#define GACLIP  (1.0f - 1e-6f)
#define GPI     3.14159274101257324f   /* float32(np.pi) */
#define GPIH    1.57079637050628662f   /* pi/2 */

// Single-MUFU approximate sqrt (rel err ~2^-21; error budget is 1e-3).
__device__ __forceinline__ float fsqrt_approx(float x)
{
    float r;
    asm("sqrt.approx.f32 %0, %1;" : "=f"(r) : "f"(x));
    return r;
}

__device__ __forceinline__ float frcp_approx(float x)
{
    float r;
    asm("rcp.approx.f32 %0, %1;" : "=f"(r) : "f"(x));
    return r;
}

// Abramowitz-Stegun 4.4.45 core: acos(xa) for xa in [0, ACLIP].
__device__ __forceinline__ float acos_core(float xa)
{
    float p = fmaf(-0.0187293f, xa, 0.0742610f);
    p = fmaf(p, xa, -0.2121144f);
    p = fmaf(p, xa, 1.5707288f);
    return fsqrt_approx(1.0f - xa) * p;
}

// acos with sign reflection via copysign (no predicate chain):
// acos(v) = pi/2 - copysign(pi/2 - acos(|v|), v)
__device__ __forceinline__ float acos_signed(float v)
{
    float ac = acos_core(fminf(fabsf(v), GACLIP));
    return GPIH - copysignf(GPIH - ac, v);
}

// Branchless circle GIoU loss; EPS/ACLIP clamps reproduce the reference's
// lens/contained/disjoint branches to ~2e-4 absolute per element.
__device__ __forceinline__ float circle_giou_loss(
    float cx0, float cy0, float r0,
    float cx1, float cy1, float r1)
{
    float dx = cx0 - cx1;
    float dy = cy0 - cy1;
    float d2  = fmaf(dx, dx, dy * dy);

    float s    = r0 + r1;
    float rd   = r0 - r1;
    float r0sq = r0 * r0;
    float r1sq = r1 * r1;
    float s2     = s * s;
    float rdiff2 = rd * rd;
    float dr2    = r0sq - r1sq;

    // One MUFU serves 1/d, 1/(d r0), 1/(d r1):
    //   spre = rsqrt(d2 * (r0 r1)^2) = 1/(d r0 r1)
    float r01   = r0 * r1;
    float spre  = rsqrtf(d2 * (r01 * r01));
    float hpre  = 0.5f * spre;
    float rinv  = r01 * spre;          // 1/d

    float v0 = (d2 + dr2) * (r1 * hpre);
    float v1 = (d2 - dr2) * (r0 * hpre);

    float a0 = acos_signed(v0);
    float a1 = acos_signed(v1);

    // sqrt(t) factored: st = sqrt(s2-d2) * sqrt(d2-rdiff2), each clamped.
    float hb  = d2 - rdiff2;
    float sh  = fsqrt_approx(fmaxf(hb, GEPS));          // also the hull term
    float st  = fsqrt_approx(fmaxf(s2 - d2, GEPS)) * sh;

    float inter = fmaf(r0sq, a0, fmaf(r1sq, a1, -0.5f * st));
    float uni   = fmaf(GPI, r0sq + r1sq, -inter);

    float q = fminf(fabsf(rd) * rinv, GACLIP);
    float alpha = acos_core(q);

    // hull = pi*rmax^2 - alpha*(rmax^2 - rmin^2) + s*sqrt(h2)
    float rmaxsq = fmaxf(r0sq, r1sq);
    float hull = fmaf(GPI, rmaxsq, fmaf(-alpha, fabsf(dr2), s * sh));

    // loss = 2 - inter/uni - uni/hull, via a single reciprocal of uni*hull.
    float rcpuh = frcp_approx(uni * hull);
    float iou   = inter * hull * rcpuh;
    float uoh   = uni * uni * rcpuh;
    return (2.0f - iou) - uoh;
}

__global__ void giou_zero_kernel(float* __restrict__ out)
{
    *out = 0.0f;
}

// 128 threads x 8 rows/thread = 1024 rows/block = 768 float4 per input.
#define BLK_F4 768

__global__ __launch_bounds__(128, 8)   // 64-reg cap, 8 CTAs/SM
void giou_kernel(const float4* __restrict__ x4,
                 const float4* __restrict__ y4,
                 float* __restrict__ out)
{
    __shared__ float4 sx[BLK_F4];
    __shared__ float4 sy[BLK_F4];

    const int      tid   = threadIdx.x;
    const unsigned base4 = blockIdx.x * (unsigned)BLK_F4;

    // Coalesced stage: warp-contiguous LDG.128 (4 wavefronts each, vs ~24
    // for the 96B-strided direct pattern), linear STS.128 (conflict-free).
    #pragma unroll
    for (int k = 0; k < 6; k++)
        sx[tid + 128 * k] = x4[base4 + tid + 128 * k];
    #pragma unroll
    for (int k = 0; k < 6; k++)
        sy[tid + 128 * k] = y4[base4 + tid + 128 * k];
    __syncthreads();

    // Each thread now reads its 8 rows (6 float4) from smem.
    const int rb = 6 * tid;
    float4 xa = sx[rb + 0], xb = sx[rb + 1], xc = sx[rb + 2];
    float4 xd = sx[rb + 3], xe = sx[rb + 4], xf = sx[rb + 5];
    float4 ya = sy[rb + 0], yb = sy[rb + 1], yc = sy[rb + 2];
    float4 yd = sy[rb + 3], ye = sy[rb + 4], yf = sy[rb + 5];

    float acc0, acc1;
    acc0  = circle_giou_loss(xa.x, xa.y, xa.z,  ya.x, ya.y, ya.z);
    acc1  = circle_giou_loss(xa.w, xb.x, xb.y,  ya.w, yb.x, yb.y);
    acc0 += circle_giou_loss(xb.z, xb.w, xc.x,  yb.z, yb.w, yc.x);
    acc1 += circle_giou_loss(xc.y, xc.z, xc.w,  yc.y, yc.z, yc.w);
    acc0 += circle_giou_loss(xd.x, xd.y, xd.z,  yd.x, yd.y, yd.z);
    acc1 += circle_giou_loss(xd.w, xe.x, xe.y,  yd.w, ye.x, ye.y);
    acc0 += circle_giou_loss(xe.z, xe.w, xf.x,  ye.z, ye.w, yf.x);
    acc1 += circle_giou_loss(xf.y, xf.z, xf.w,  yf.y, yf.z, yf.w);
    float acc = acc0 + acc1;

    // Warp reduce (4 warps)
    #pragma unroll
    for (int off = 16; off > 0; off >>= 1)
        acc += __shfl_down_sync(0xffffffffu, acc, off);

    __shared__ float warp_sums[4];
    const int lane = tid & 31;
    const int warp = tid >> 5;
    if (lane == 0) warp_sums[warp] = acc;
    __syncthreads();

    if (tid == 0) {
        float v = warp_sums[0] + warp_sums[1] + warp_sums[2] + warp_sums[3];
        atomicAdd(out, v);
    }
}

extern "C" void kernel_launch(void* const* d_in, const int* in_sizes, int n_in,
                              void* d_out, int out_size)
{
    const float4* x4 = (const float4*)d_in[0];
    const float4* y4 = (const float4*)d_in[1];
    float* out = (float*)d_out;

    const int n_rows = in_sizes[0] / 3;          // 4194304
    const int threads = 128;
    const int rows_per_block = threads * 8;      // 1024
    const int blocks = (n_rows + rows_per_block - 1) / rows_per_block;  // 4096

    giou_zero_kernel<<<1, 1>>>(out);
    giou_kernel<<<blocks, threads>>>(x4, y4, out);
}

// round 13
// speedup vs baseline: 1.0976x; 1.0976x over previous
#include <cuda_runtime.h>

#define GEPS    1e-7f
#define GACLIP  (1.0f - 1e-6f)
#define GPI     3.14159274101257324f   /* float32(np.pi) */
#define GPIH    1.57079637050628662f   /* pi/2 */

// Single-MUFU approximate sqrt (rel err ~2^-21; error budget is 1e-3).
__device__ __forceinline__ float fsqrt_approx(float x)
{
    float r;
    asm("sqrt.approx.f32 %0, %1;" : "=f"(r) : "f"(x));
    return r;
}

__device__ __forceinline__ float frcp_approx(float x)
{
    float r;
    asm("rcp.approx.f32 %0, %1;" : "=f"(r) : "f"(x));
    return r;
}

// Abramowitz-Stegun 4.4.45 core: acos(xa) for xa in [0, ACLIP].
__device__ __forceinline__ float acos_core(float xa)
{
    float p = fmaf(-0.0187293f, xa, 0.0742610f);
    p = fmaf(p, xa, -0.2121144f);
    p = fmaf(p, xa, 1.5707288f);
    return fsqrt_approx(1.0f - xa) * p;
}

// acos with sign reflection via copysign (no predicate chain):
// acos(v) = pi/2 - copysign(pi/2 - acos(|v|), v)
__device__ __forceinline__ float acos_signed(float v)
{
    float ac = acos_core(fminf(fabsf(v), GACLIP));
    return GPIH - copysignf(GPIH - ac, v);
}

// Branchless circle GIoU loss; EPS/ACLIP clamps reproduce the reference's
// lens/contained/disjoint branches to ~2e-4 absolute per element.
__device__ __forceinline__ float circle_giou_loss(
    float cx0, float cy0, float r0,
    float cx1, float cy1, float r1)
{
    float dx = cx0 - cx1;
    float dy = cy0 - cy1;
    float d2  = fmaf(dx, dx, dy * dy);

    float s    = r0 + r1;
    float rd   = r0 - r1;
    float r0sq = r0 * r0;
    float r1sq = r1 * r1;
    float s2     = s * s;
    float rdiff2 = rd * rd;
    float dr2    = r0sq - r1sq;

    // One MUFU serves 1/d, 1/(d r0), 1/(d r1):
    //   spre = rsqrt(d2 * (r0 r1)^2) = 1/(d r0 r1)
    float r01   = r0 * r1;
    float spre  = rsqrtf(d2 * (r01 * r01));
    float hpre  = 0.5f * spre;
    float rinv  = r01 * spre;          // 1/d

    float v0 = (d2 + dr2) * (r1 * hpre);
    float v1 = (d2 - dr2) * (r0 * hpre);

    float a0 = acos_signed(v0);
    float a1 = acos_signed(v1);

    // sqrt(t) factored: st = sqrt(s2-d2) * sqrt(d2-rdiff2), each clamped.
    float hb  = d2 - rdiff2;
    float sh  = fsqrt_approx(fmaxf(hb, GEPS));          // also the hull term
    float st  = fsqrt_approx(fmaxf(s2 - d2, GEPS)) * sh;

    float inter = fmaf(r0sq, a0, fmaf(r1sq, a1, -0.5f * st));
    float uni   = fmaf(GPI, r0sq + r1sq, -inter);

    float q = fminf(fabsf(rd) * rinv, GACLIP);
    float alpha = acos_core(q);

    // hull = pi*rmax^2 - alpha*(rmax^2 - rmin^2) + s*sqrt(h2)
    float rmaxsq = fmaxf(r0sq, r1sq);
    float hull = fmaf(GPI, rmaxsq, fmaf(-alpha, fabsf(dr2), s * sh));

    // loss = 2 - inter/uni - uni/hull, via a single reciprocal of uni*hull.
    float rcpuh = frcp_approx(uni * hull);
    float iou   = inter * hull * rcpuh;
    float uoh   = uni * uni * rcpuh;
    return (2.0f - iou) - uoh;
}

__global__ void giou_zero_kernel(float* __restrict__ out)
{
    *out = 0.0f;
}

__global__ __launch_bounds__(256, 5)   // 51-reg cap: 5 CTAs/SM, occ 62.5%
void giou_kernel(const float4* __restrict__ x4,
                 const float4* __restrict__ y4,
                 float* __restrict__ out)
{
    const unsigned tid = blockIdx.x * blockDim.x + threadIdx.x;

    // 4 rows/thread = 3 float4 per input (48B stride: half the L1tex
    // wavefront load of the 8-row variant). All 6 loads batched up front.
    const unsigned base = 3u * tid;
    float4 xa = x4[base + 0];
    float4 xb = x4[base + 1];
    float4 xc = x4[base + 2];
    float4 ya = y4[base + 0];
    float4 yb = y4[base + 1];
    float4 yc = y4[base + 2];

    float acc0, acc1;
    acc0  = circle_giou_loss(xa.x, xa.y, xa.z,  ya.x, ya.y, ya.z);
    acc1  = circle_giou_loss(xa.w, xb.x, xb.y,  ya.w, yb.x, yb.y);
    acc0 += circle_giou_loss(xb.z, xb.w, xc.x,  yb.z, yb.w, yc.x);
    acc1 += circle_giou_loss(xc.y, xc.z, xc.w,  yc.y, yc.z, yc.w);
    float acc = acc0 + acc1;

    // Warp reduce
    #pragma unroll
    for (int off = 16; off > 0; off >>= 1)
        acc += __shfl_down_sync(0xffffffffu, acc, off);

    __shared__ float warp_sums[8];
    const int lane = threadIdx.x & 31;
    const int warp = threadIdx.x >> 5;
    if (lane == 0) warp_sums[warp] = acc;
    __syncthreads();

    if (threadIdx.x < 8) {
        float v = warp_sums[threadIdx.x];
        #pragma unroll
        for (int off = 4; off > 0; off >>= 1)
            v += __shfl_down_sync(0xffu, v, off);
        if (threadIdx.x == 0)
            atomicAdd(out, v);
    }
}

extern "C" void kernel_launch(void* const* d_in, const int* in_sizes, int n_in,
                              void* d_out, int out_size)
{
    const float4* x4 = (const float4*)d_in[0];
    const float4* y4 = (const float4*)d_in[1];
    float* out = (float*)d_out;

    const int n_rows = in_sizes[0] / 3;          // 4194304
    const int threads = 256;
    const int rows_per_block = threads * 4;      // 1024
    const int blocks = (n_rows + rows_per_block - 1) / rows_per_block;  // 4096

    giou_zero_kernel<<<1, 1>>>(out);
    giou_kernel<<<blocks, threads>>>(x4, y4, out);
}

// round 14
// speedup vs baseline: 1.1980x; 1.0915x over previous
#include <cuda_runtime.h>

#define GEPS    1e-7f
#define GACLIP  (1.0f - 1e-6f)
#define GPI     3.14159274101257324f   /* float32(np.pi) */
#define GPIH    1.57079637050628662f   /* pi/2 */

// Single-MUFU approximate sqrt (rel err ~2^-21; error budget is 1e-3).
__device__ __forceinline__ float fsqrt_approx(float x)
{
    float r;
    asm("sqrt.approx.f32 %0, %1;" : "=f"(r) : "f"(x));
    return r;
}

// Abramowitz-Stegun 4.4.45 core: acos(xa) for xa in [0, ACLIP].
__device__ __forceinline__ float acos_core(float xa)
{
    float p = fmaf(-0.0187293f, xa, 0.0742610f);
    p = fmaf(p, xa, -0.2121144f);
    p = fmaf(p, xa, 1.5707288f);
    return fsqrt_approx(1.0f - xa) * p;
}

// Branchless circle GIoU loss; EPS/ACLIP clamps reproduce the reference's
// lens/contained/disjoint branches to ~2e-4 absolute per element.
// Uses acos(v) = pi/2 - cs, cs = copysign(pi/2 - acos(|v|), v), folded so
// inter = g - T, uni = g + T with g = (pi/2)*sumsq.
__device__ __forceinline__ float circle_giou_loss(
    float cx0, float cy0, float r0,
    float cx1, float cy1, float r1)
{
    float dx = cx0 - cx1;
    float dy = cy0 - cy1;
    float d2  = fmaf(dx, dx, dy * dy);

    float s    = r0 + r1;
    float rd   = r0 - r1;
    float r0sq = r0 * r0;
    float r1sq = r1 * r1;
    float s2     = s * s;
    float rdiff2 = rd * rd;
    float dr2    = r0sq - r1sq;

    // One MUFU serves 1/d, 1/(d r0), 1/(d r1):
    //   spre = rsqrt(d2 * (r0 r1)^2) = 1/(d r0 r1)
    float r01   = r0 * r1;
    float spre  = rsqrtf(d2 * (r01 * r01));
    float hpre  = 0.5f * spre;
    float rinv  = r01 * spre;          // 1/d

    float v0 = (d2 + dr2) * (r1 * hpre);
    float v1 = (d2 - dr2) * (r0 * hpre);

    float ac0 = acos_core(fminf(fabsf(v0), GACLIP));
    float ac1 = acos_core(fminf(fabsf(v1), GACLIP));
    float cs0 = copysignf(GPIH - ac0, v0);
    float cs1 = copysignf(GPIH - ac1, v1);

    // sqrt(t) factored: st = sqrt(s2-d2) * sqrt(d2-rdiff2), each clamped.
    float hb  = d2 - rdiff2;
    float sh  = fsqrt_approx(fmaxf(hb, GEPS));          // also the hull term
    float st  = fsqrt_approx(fmaxf(s2 - d2, GEPS)) * sh;

    float sumsq = r0sq + r1sq;
    float g = GPIH * sumsq;
    float T = fmaf(r0sq, cs0, fmaf(r1sq, cs1, 0.5f * st));
    float inter = g - T;
    float uni   = g + T;

    float q = fminf(fabsf(rd) * rinv, GACLIP);
    float alpha = acos_core(q);

    // hull = pi*rmax^2 - alpha*(rmax^2 - rmin^2) + s*sqrt(h2)
    float rmaxsq = fmaxf(r0sq, r1sq);
    float hull = fmaf(GPI, rmaxsq, fmaf(-alpha, fabsf(dr2), s * sh));

    // loss = 2 - inter/uni - uni/hull
    return (2.0f - __fdividef(inter, uni)) - __fdividef(uni, hull);
}

__global__ void giou_zero_kernel(float* __restrict__ out)
{
    *out = 0.0f;
}

// 2048 blocks x 256 threads; each thread does two FAR 4-row chunks:
// chunk A in the first half of the array, chunk B in the second half.
// Lane stride stays 48B (12 lines/LDG) while 12 loads batch up front.
#define HALF_F4 1572864   /* (N/2 rows) * 3 / 4 = 2097152*3/4 float4s */

__global__ __launch_bounds__(256, 3)   // 85-reg cap: loads provably hoist
void giou_kernel(const float4* __restrict__ x4,
                 const float4* __restrict__ y4,
                 float* __restrict__ out)
{
    const unsigned tid = blockIdx.x * blockDim.x + threadIdx.x;

    const unsigned baseA = 3u * tid;
    const unsigned baseB = baseA + (unsigned)HALF_F4;

    // All 12 float4 loads batched up front (MLP=12, 48B lane stride).
    float4 xa = x4[baseA + 0], xb = x4[baseA + 1], xc = x4[baseA + 2];
    float4 xd = x4[baseB + 0], xe = x4[baseB + 1], xf = x4[baseB + 2];
    float4 ya = y4[baseA + 0], yb = y4[baseA + 1], yc = y4[baseA + 2];
    float4 yd = y4[baseB + 0], ye = y4[baseB + 1], yf = y4[baseB + 2];

    float acc0, acc1;
    acc0  = circle_giou_loss(xa.x, xa.y, xa.z,  ya.x, ya.y, ya.z);
    acc1  = circle_giou_loss(xa.w, xb.x, xb.y,  ya.w, yb.x, yb.y);
    acc0 += circle_giou_loss(xb.z, xb.w, xc.x,  yb.z, yb.w, yc.x);
    acc1 += circle_giou_loss(xc.y, xc.z, xc.w,  yc.y, yc.z, yc.w);
    acc0 += circle_giou_loss(xd.x, xd.y, xd.z,  yd.x, yd.y, yd.z);
    acc1 += circle_giou_loss(xd.w, xe.x, xe.y,  yd.w, ye.x, ye.y);
    acc0 += circle_giou_loss(xe.z, xe.w, xf.x,  ye.z, ye.w, yf.x);
    acc1 += circle_giou_loss(xf.y, xf.z, xf.w,  yf.y, yf.z, yf.w);
    float acc = acc0 + acc1;

    // Warp reduce
    #pragma unroll
    for (int off = 16; off > 0; off >>= 1)
        acc += __shfl_down_sync(0xffffffffu, acc, off);

    __shared__ float warp_sums[8];
    const int lane = threadIdx.x & 31;
    const int warp = threadIdx.x >> 5;
    if (lane == 0) warp_sums[warp] = acc;
    __syncthreads();

    if (threadIdx.x < 8) {
        float v = warp_sums[threadIdx.x];
        #pragma unroll
        for (int off = 4; off > 0; off >>= 1)
            v += __shfl_down_sync(0xffu, v, off);
        if (threadIdx.x == 0)
            atomicAdd(out, v);
    }
}

extern "C" void kernel_launch(void* const* d_in, const int* in_sizes, int n_in,
                              void* d_out, int out_size)
{
    const float4* x4 = (const float4*)d_in[0];
    const float4* y4 = (const float4*)d_in[1];
    float* out = (float*)d_out;

    const int n_rows = in_sizes[0] / 3;          // 4194304
    const int threads = 256;
    const int rows_per_block = threads * 8;      // 2048
    const int blocks = (n_rows + rows_per_block - 1) / rows_per_block;  // 2048

    giou_zero_kernel<<<1, 1>>>(out);
    giou_kernel<<<blocks, threads>>>(x4, y4, out);
}

// round 15
// speedup vs baseline: 1.2000x; 1.0017x over previous
#include <cuda_runtime.h>

#define GEPS    1e-7f
#define GACLIP  (1.0f - 1e-6f)
#define GPI     3.14159274101257324f   /* float32(np.pi) */
#define GPIH    1.57079637050628662f   /* pi/2 */

// Single-MUFU approximate sqrt (rel err ~2^-21; error budget is 1e-3).
__device__ __forceinline__ float fsqrt_approx(float x)
{
    float r;
    asm("sqrt.approx.f32 %0, %1;" : "=f"(r) : "f"(x));
    return r;
}

// Abramowitz-Stegun 4.4.45 core: acos(xa) for xa in [0, ACLIP].
__device__ __forceinline__ float acos_core(float xa)
{
    float p = fmaf(-0.0187293f, xa, 0.0742610f);
    p = fmaf(p, xa, -0.2121144f);
    p = fmaf(p, xa, 1.5707288f);
    return fsqrt_approx(1.0f - xa) * p;
}

// Branchless circle GIoU loss; EPS/ACLIP clamps reproduce the reference's
// lens/contained/disjoint branches to ~2e-4 absolute per element.
// Uses acos(v) = pi/2 - cs, cs = copysign(pi/2 - acos(|v|), v), folded so
// inter = g - T, uni = g + T with g = (pi/2)*sumsq.
__device__ __forceinline__ float circle_giou_loss(
    float cx0, float cy0, float r0,
    float cx1, float cy1, float r1)
{
    float dx = cx0 - cx1;
    float dy = cy0 - cy1;
    float d2  = fmaf(dx, dx, dy * dy);

    float s    = r0 + r1;
    float rd   = r0 - r1;
    float r0sq = r0 * r0;
    float r1sq = r1 * r1;
    float s2     = s * s;
    float rdiff2 = rd * rd;
    float dr2    = r0sq - r1sq;

    // One MUFU serves 1/d, 1/(d r0), 1/(d r1):
    //   spre = rsqrt(d2 * (r0 r1)^2) = 1/(d r0 r1)
    float r01   = r0 * r1;
    float spre  = rsqrtf(d2 * (r01 * r01));
    float hpre  = 0.5f * spre;
    float rinv  = r01 * spre;          // 1/d

    float v0 = (d2 + dr2) * (r1 * hpre);
    float v1 = (d2 - dr2) * (r0 * hpre);

    float ac0 = acos_core(fminf(fabsf(v0), GACLIP));
    float ac1 = acos_core(fminf(fabsf(v1), GACLIP));
    float cs0 = copysignf(GPIH - ac0, v0);
    float cs1 = copysignf(GPIH - ac1, v1);

    // sqrt(t) factored: st = sqrt(s2-d2) * sqrt(d2-rdiff2), each clamped.
    float hb  = d2 - rdiff2;
    float sh  = fsqrt_approx(fmaxf(hb, GEPS));          // also the hull term
    float st  = fsqrt_approx(fmaxf(s2 - d2, GEPS)) * sh;

    float sumsq = r0sq + r1sq;
    float g = GPIH * sumsq;
    float T = fmaf(r0sq, cs0, fmaf(r1sq, cs1, 0.5f * st));
    float inter = g - T;
    float uni   = g + T;

    float q = fminf(fabsf(rd) * rinv, GACLIP);
    float alpha = acos_core(q);

    // hull = pi*rmax^2 - alpha*(rmax^2 - rmin^2) + s*sqrt(h2)
    float rmaxsq = fmaxf(r0sq, r1sq);
    float hull = fmaf(GPI, rmaxsq, fmaf(-alpha, fabsf(dr2), s * sh));

    // loss = 2 - inter/uni - uni/hull
    return (2.0f - __fdividef(inter, uni)) - __fdividef(uni, hull);
}

__global__ void giou_zero_kernel(float* __restrict__ out)
{
    *out = 0.0f;
}

// 2048 blocks x 256 threads; each thread does two FAR 4-row chunks:
// chunk A in the first half of the array, chunk B in the second half.
// Lane stride stays 48B (12 lines/LDG) while 12 loads batch up front.
#define HALF_F4 1572864   /* (N/2 rows) * 3 / 4 = 2097152*3/4 float4s */

__global__ __launch_bounds__(256, 4)   // 64-reg cap: testing 4 CTAs/SM
void giou_kernel(const float4* __restrict__ x4,
                 const float4* __restrict__ y4,
                 float* __restrict__ out)
{
    const unsigned tid = blockIdx.x * blockDim.x + threadIdx.x;

    const unsigned baseA = 3u * tid;
    const unsigned baseB = baseA + (unsigned)HALF_F4;

    // All 12 float4 loads batched up front (MLP=12, 48B lane stride).
    float4 xa = x4[baseA + 0], xb = x4[baseA + 1], xc = x4[baseA + 2];
    float4 xd = x4[baseB + 0], xe = x4[baseB + 1], xf = x4[baseB + 2];
    float4 ya = y4[baseA + 0], yb = y4[baseA + 1], yc = y4[baseA + 2];
    float4 yd = y4[baseB + 0], ye = y4[baseB + 1], yf = y4[baseB + 2];

    float acc0, acc1;
    acc0  = circle_giou_loss(xa.x, xa.y, xa.z,  ya.x, ya.y, ya.z);
    acc1  = circle_giou_loss(xa.w, xb.x, xb.y,  ya.w, yb.x, yb.y);
    acc0 += circle_giou_loss(xb.z, xb.w, xc.x,  yb.z, yb.w, yc.x);
    acc1 += circle_giou_loss(xc.y, xc.z, xc.w,  yc.y, yc.z, yc.w);
    acc0 += circle_giou_loss(xd.x, xd.y, xd.z,  yd.x, yd.y, yd.z);
    acc1 += circle_giou_loss(xd.w, xe.x, xe.y,  yd.w, ye.x, ye.y);
    acc0 += circle_giou_loss(xe.z, xe.w, xf.x,  ye.z, ye.w, yf.x);
    acc1 += circle_giou_loss(xf.y, xf.z, xf.w,  yf.y, yf.z, yf.w);
    float acc = acc0 + acc1;

    // Warp reduce
    #pragma unroll
    for (int off = 16; off > 0; off >>= 1)
        acc += __shfl_down_sync(0xffffffffu, acc, off);

    __shared__ float warp_sums[8];
    const int lane = threadIdx.x & 31;
    const int warp = threadIdx.x >> 5;
    if (lane == 0) warp_sums[warp] = acc;
    __syncthreads();

    if (threadIdx.x < 8) {
        float v = warp_sums[threadIdx.x];
        #pragma unroll
        for (int off = 4; off > 0; off >>= 1)
            v += __shfl_down_sync(0xffu, v, off);
        if (threadIdx.x == 0)
            atomicAdd(out, v);
    }
}

extern "C" void kernel_launch(void* const* d_in, const int* in_sizes, int n_in,
                              void* d_out, int out_size)
{
    const float4* x4 = (const float4*)d_in[0];
    const float4* y4 = (const float4*)d_in[1];
    float* out = (float*)d_out;

    const int n_rows = in_sizes[0] / 3;          // 4194304
    const int threads = 256;
    const int rows_per_block = threads * 8;      // 2048
    const int blocks = (n_rows + rows_per_block - 1) / rows_per_block;  // 2048

    giou_zero_kernel<<<1, 1>>>(out);
    giou_kernel<<<blocks, threads>>>(x4, y4, out);
}